// round 3
// baseline (speedup 1.0000x reference)
#include <cuda_runtime.h>
#include <cstdint>
#include <cstddef>
#include <math.h>

#define Bb 32
#define Tt 1024
#define Dd 512
#define Hh 512
#define R4 4096
#define NBLK 128
#define NTHR 128

// ---- static device scratch (allocations are forbidden) ----
__device__ float    g_P[(size_t)Tt * R4 * Bb];   // [t][r][b], r = cell*2048 + gate*512 + j
__device__ float    g_H[2][2][Hh][Bb];           // [pingpong][cell][j][b]
__device__ float    g_XH[2][Tt][Bb];             // x_hat after sub1/sub2
__device__ unsigned g_bar;

__device__ __forceinline__ float sigf(float x) { return 1.0f / (1.0f + expf(-x)); }

// =====================================================================
// Kernel 1: P[t][r][b] = sum_d U[b][t][d]*Wih[r][d] + bih[r] + bhh[r]
// grid (32, 1024), 256 thr; tile 128 rows x 32 batches, K-tiled by 32.
// =====================================================================
__global__ __launch_bounds__(256) void pre_kernel(
    const float* __restrict__ U,
    const float* __restrict__ wih_f, const float* __restrict__ wih_b,
    const float* __restrict__ bih_f, const float* __restrict__ bhh_f,
    const float* __restrict__ bih_b, const float* __restrict__ bhh_b)
{
    __shared__ float Us[32][36];    // [k][b]
    __shared__ float Ws[32][132];   // [k][r]

    const int t  = blockIdx.y;
    const int r0 = blockIdx.x * 128;
    const int cb = (r0 >= 2048);
    const float* wih = cb ? wih_b : wih_f;
    const int rbase = r0 - cb * 2048;

    const int tid = threadIdx.x;
    const int b0  = (tid & 7) * 4;
    const int rr0 = ((tid >> 3) & 31) * 4;

    float acc[4][4];
#pragma unroll
    for (int i = 0; i < 4; ++i)
#pragma unroll
        for (int j = 0; j < 4; ++j) acc[i][j] = 0.0f;

    for (int kt = 0; kt < 16; ++kt) {
        const int k0 = kt * 32;
        {   // U tile: 32 b x 32 k -> Us[k][b]
            int bb = tid >> 3, kq = tid & 7;
            float4 v = *(const float4*)&U[(size_t)bb * (Tt * Dd) + (size_t)t * Dd + k0 + kq * 4];
            Us[kq * 4 + 0][bb] = v.x; Us[kq * 4 + 1][bb] = v.y;
            Us[kq * 4 + 2][bb] = v.z; Us[kq * 4 + 3][bb] = v.w;
        }
#pragma unroll
        for (int ii = 0; ii < 4; ++ii) {  // W tile: 128 r x 32 k -> Ws[k][r]
            int rr = (tid >> 3) + 32 * ii, kq = tid & 7;
            float4 v = *(const float4*)&wih[(size_t)(rbase + rr) * Dd + k0 + kq * 4];
            Ws[kq * 4 + 0][rr] = v.x; Ws[kq * 4 + 1][rr] = v.y;
            Ws[kq * 4 + 2][rr] = v.z; Ws[kq * 4 + 3][rr] = v.w;
        }
        __syncthreads();
#pragma unroll
        for (int k = 0; k < 32; ++k) {
            float4 ub = *(const float4*)&Us[k][b0];
            float4 wr = *(const float4*)&Ws[k][rr0];
            acc[0][0] += wr.x*ub.x; acc[0][1] += wr.x*ub.y; acc[0][2] += wr.x*ub.z; acc[0][3] += wr.x*ub.w;
            acc[1][0] += wr.y*ub.x; acc[1][1] += wr.y*ub.y; acc[1][2] += wr.y*ub.z; acc[1][3] += wr.y*ub.w;
            acc[2][0] += wr.z*ub.x; acc[2][1] += wr.z*ub.y; acc[2][2] += wr.z*ub.z; acc[2][3] += wr.z*ub.w;
            acc[3][0] += wr.w*ub.x; acc[3][1] += wr.w*ub.y; acc[3][2] += wr.w*ub.z; acc[3][3] += wr.w*ub.w;
        }
        __syncthreads();
    }
#pragma unroll
    for (int i = 0; i < 4; ++i) {
        int rw = rbase + rr0 + i;
        float bias = cb ? (bih_b[rw] + bhh_b[rw]) : (bih_f[rw] + bhh_f[rw]);
        float4 o = make_float4(acc[i][0]+bias, acc[i][1]+bias, acc[i][2]+bias, acc[i][3]+bias);
        *(float4*)&g_P[((size_t)t * R4 + (size_t)(r0 + rr0 + i)) * Bb + b0] = o;
    }
}

// =====================================================================
// Kernel 2: persistent recurrence. 128 blocks x 128 threads, 1 blk/SM.
// block -> (cell, 8 j's); warp w -> j's {j0+2w, j0+2w+1} x 4 gates; lane = b.
// =====================================================================
__global__ void __launch_bounds__(NTHR, 1) rec_kernel(
    const float* __restrict__ whh_f, const float* __restrict__ whh_b,
    const float* __restrict__ wih_f, const float* __restrict__ wih_b)
{
    extern __shared__ float sm[];
    float* ws   = sm;                 // [32 local rows][512]
    float* hs   = sm + 32 * 512;      // [512 j][32 b]
    float* rsum = hs + 512 * 32;      // [32]
    float* red  = rsum + 32;          // [128]

    const int tid  = threadIdx.x;
    const int w    = tid >> 5;
    const int b    = tid & 31;
    const int cell = blockIdx.x >> 6;
    const int g    = blockIdx.x & 63;
    const int j0   = g * 8;
    const int jA   = j0 + 2 * w;

    const float* whh = cell ? whh_b : whh_f;
    const float* wih = cell ? wih_b : wih_f;

    // Whh rows -> SMEM; local row rl = w*8 + jj*4 + gate
    for (int idx = tid * 4; idx < 32 * 512; idx += NTHR * 4) {
        int rl = idx >> 9, k = idx & 511;
        int w_ = rl >> 3, rem = rl & 7, jj = rem >> 2, gate = rem & 3;
        int grow = gate * 512 + (j0 + 2 * w_ + jj);
        *(float4*)&ws[idx] = *(const float4*)&whh[(size_t)grow * 512 + k];
    }
    {   // rowsums of Wih (scalar-broadcast input of sub-step 2)
        int rl = tid & 31, part = tid >> 5;
        int w_ = rl >> 3, rem = rl & 7, jj = rem >> 2, gate = rem & 3;
        int grow = gate * 512 + (j0 + 2 * w_ + jj);
        float s = 0.0f;
        const float* p = &wih[(size_t)grow * 512 + part * 128];
#pragma unroll 4
        for (int k = 0; k < 128; k += 4) {
            float4 v = *(const float4*)&p[k];
            s += v.x + v.y + v.z + v.w;
        }
        red[tid] = s;
    }
    __syncthreads();
    if (tid < 32) rsum[tid] = red[tid] + red[tid + 32] + red[tid + 64] + red[tid + 96];

    float c0 = 0.0f, c1 = 0.0f;
    const float* wbase = ws + (w * 8) * 512;
    volatile unsigned* vbar = &g_bar;

    for (int step = 0; step < 2 * Tt; ++step) {
        const int t = step >> 1, sub = step & 1;
        const int rbuf = step & 1, wbuf = rbuf ^ 1;

        if (step == 0) {
            for (int i = tid; i < 512 * 32; i += NTHR) hs[i] = 0.0f;
        } else {
            const float* src = &g_H[rbuf][cell][0][0];
            for (int i = tid * 4; i < 512 * 32; i += NTHR * 4)
                *(float4*)&hs[i] = *(const float4*)&src[i];
        }
        float xh = sub ? g_H[rbuf][1][Hh - 1][b] : 0.0f;

        // prefetch P (DRAM) so latency overlaps the matvec
        float pv[8];
        {
            const float* Pt = g_P + ((size_t)t * R4 + (size_t)cell * 2048) * Bb;
#pragma unroll
            for (int r = 0; r < 8; ++r) {
                int jj = r >> 2, gate = r & 3;
                pv[r] = Pt[(size_t)(gate * 512 + jA + jj) * Bb + b];
            }
        }
        __syncthreads();

        float acc[8];
#pragma unroll
        for (int r = 0; r < 8; ++r) acc[r] = 0.0f;
#pragma unroll 2
        for (int k = 0; k < 512; k += 4) {
            float h0 = hs[(k + 0) * 32 + b];
            float h1 = hs[(k + 1) * 32 + b];
            float h2 = hs[(k + 2) * 32 + b];
            float h3 = hs[(k + 3) * 32 + b];
#pragma unroll
            for (int r = 0; r < 8; ++r) {
                float4 wv = *(const float4*)&wbase[r * 512 + k];
                acc[r] += wv.x * h0;
                acc[r] += wv.y * h1;
                acc[r] += wv.z * h2;
                acc[r] += wv.w * h3;
            }
        }
#pragma unroll
        for (int jj = 0; jj < 2; ++jj) {
            float iv = acc[jj*4+0] + pv[jj*4+0];
            float fv = acc[jj*4+1] + pv[jj*4+1];
            float gv = acc[jj*4+2] + pv[jj*4+2];
            float ov = acc[jj*4+3] + pv[jj*4+3];
            if (sub) {
                iv += xh * rsum[w*8 + jj*4 + 0];
                fv += xh * rsum[w*8 + jj*4 + 1];
                gv += xh * rsum[w*8 + jj*4 + 2];
                ov += xh * rsum[w*8 + jj*4 + 3];
            }
            float cp = jj ? c1 : c0;
            float c2 = sigf(fv) * cp + sigf(iv) * tanhf(gv);
            float h2 = sigf(ov) * tanhf(c2);
            if (jj) c1 = c2; else c0 = c2;
            int j = jA + jj;
            g_H[wbuf][cell][j][b] = h2;
            if (cell == 1 && j == Hh - 1) g_XH[sub][t][b] = h2;
        }

        if (step == 2 * Tt - 1) break;
        __threadfence();
        __syncthreads();
        if (tid == 0) {
            atomicAdd(&g_bar, 1u);
            unsigned want = (unsigned)(step + 1) * NBLK;
            while (*vbar < want) __nanosleep(64);
        }
        __syncthreads();
        __threadfence();
    }
}

// =====================================================================
// Kernel 3: out = 1.5*u + 0.5*xh1 + 0.5*xh2   (xh broadcast over D)
// =====================================================================
__global__ __launch_bounds__(256) void epi_kernel(const float* __restrict__ U,
                                                  float* __restrict__ out)
{
    int idx = blockIdx.x * blockDim.x + threadIdx.x;   // float4 index
    if (idx >= Bb * Tt * Dd / 4) return;
    int t = (idx >> 7) & (Tt - 1);
    int b = idx >> 17;
    float s = 0.5f * (g_XH[0][t][b] + g_XH[1][t][b]);
    float4 u = ((const float4*)U)[idx];
    float4 o = make_float4(1.5f*u.x + s, 1.5f*u.y + s, 1.5f*u.z + s, 1.5f*u.w + s);
    ((float4*)out)[idx] = o;
}

extern "C" void kernel_launch(void* const* d_in, const int* in_sizes, int n_in,
                              void* d_out, int out_size) {
    const float* U     = (const float*)d_in[0];
    const float* wih_f = (const float*)d_in[1];
    const float* whh_f = (const float*)d_in[2];
    const float* bih_f = (const float*)d_in[3];
    const float* bhh_f = (const float*)d_in[4];
    const float* wih_b = (const float*)d_in[5];
    const float* whh_b = (const float*)d_in[6];
    const float* bih_b = (const float*)d_in[7];
    const float* bhh_b = (const float*)d_in[8];
    float* out = (float*)d_out;

    static int smem_sz = 32*512*4 + 512*32*4 + (32 + NTHR) * 4;
    cudaFuncSetAttribute(rec_kernel, cudaFuncAttributeMaxDynamicSharedMemorySize, smem_sz);

    void* bar_addr = nullptr;
    cudaGetSymbolAddress(&bar_addr, g_bar);
    cudaMemsetAsync(bar_addr, 0, sizeof(unsigned), 0);

    pre_kernel<<<dim3(32, Tt), 256>>>(U, wih_f, wih_b, bih_f, bhh_f, bih_b, bhh_b);
    rec_kernel<<<NBLK, NTHR, smem_sz>>>(whh_f, whh_b, wih_f, wih_b);
    epi_kernel<<<(Bb * Tt * Dd / 4 + 255) / 256, 256>>>(U, out);
}

// round 4
// speedup vs baseline: 1.0211x; 1.0211x over previous
#include <cuda_runtime.h>
#include <cstdint>
#include <cstddef>
#include <math.h>

#define Bb 32
#define Tt 1024
#define Dd 512
#define Hh 512
#define R4 4096
#define NBLK 128
#define NTHR 256

typedef unsigned long long u64;

__device__ float    g_P[(size_t)Tt * R4 * Bb];      // [t][r][b], r = cell*2048+gate*512+j
__device__ float    g_H[2][2][Hh/2][Bb][2];         // [pp][cell][j/2][b][j&1] (k-pair packed)
__device__ float    g_XH[2][Tt][Bb];
__device__ unsigned g_bar;

__device__ __forceinline__ u64 pk(float lo, float hi) {
    u64 r; asm("mov.b64 %0,{%1,%2};" : "=l"(r) : "f"(lo), "f"(hi)); return r;
}
__device__ __forceinline__ void unpk(u64 v, float& lo, float& hi) {
    asm("mov.b64 {%0,%1},%2;" : "=f"(lo), "=f"(hi) : "l"(v));
}
__device__ __forceinline__ void fma2(u64& d, u64 a, u64 b) {
    asm("fma.rn.f32x2 %0,%1,%2,%0;" : "+l"(d) : "l"(a), "l"(b));
}
__device__ __forceinline__ float fsig(float x) {
    x = fminf(fmaxf(x, -30.0f), 30.0f);
    return __fdividef(1.0f, 1.0f + __expf(-x));
}
__device__ __forceinline__ float ftanh(float x) {
    x = fminf(fmaxf(x, -15.0f), 15.0f);
    float e = __expf(2.0f * x);
    return __fdividef(e - 1.0f, e + 1.0f);
}

// =====================================================================
// Kernel 1: P[t][r][b] = sum_d U[b][t][d]*Wih[r][d] + bih[r] + bhh[r]
// grid (32,1024) x 256 thr; tile 128 rows x 32 b; K-tiled by 32, FFMA2.
// =====================================================================
__global__ __launch_bounds__(256) void pre_kernel(
    const float* __restrict__ U,
    const float* __restrict__ wih_f, const float* __restrict__ wih_b,
    const float* __restrict__ bih_f, const float* __restrict__ bhh_f,
    const float* __restrict__ bih_b, const float* __restrict__ bhh_b)
{
    __shared__ u64 Usp[16][34];    // [kpair][b]   {u_k,u_k+1}
    __shared__ u64 Wsp[16][134];   // [kpair][row] {w_k,w_k+1}

    const int t  = blockIdx.y;
    const int r0 = blockIdx.x * 128;
    const int cb = (r0 >= 2048);
    const float* wih = cb ? wih_b : wih_f;
    const int rbase = r0 - cb * 2048;

    const int tid = threadIdx.x;
    const int b0  = (tid & 7) * 4;
    const int rr0 = ((tid >> 3) & 31) * 4;

    u64 a[4][4];
#pragma unroll
    for (int i = 0; i < 4; ++i)
#pragma unroll
        for (int j = 0; j < 4; ++j) a[i][j] = 0ULL;

    for (int kt = 0; kt < 16; ++kt) {
        const int k0 = kt * 32;
        {   // U tile 32b x 32k -> kpair-packed
            int bb = tid >> 3, kq = tid & 7;
            float4 v = *(const float4*)&U[(size_t)bb * (Tt * Dd) + (size_t)t * Dd + k0 + kq * 4];
            Usp[kq * 2 + 0][bb] = pk(v.x, v.y);
            Usp[kq * 2 + 1][bb] = pk(v.z, v.w);
        }
#pragma unroll
        for (int ii = 0; ii < 4; ++ii) {   // W tile 128r x 32k
            int rr = (tid >> 3) + 32 * ii, kq = tid & 7;
            float4 v = *(const float4*)&wih[(size_t)(rbase + rr) * Dd + k0 + kq * 4];
            Wsp[kq * 2 + 0][rr] = pk(v.x, v.y);
            Wsp[kq * 2 + 1][rr] = pk(v.z, v.w);
        }
        __syncthreads();
#pragma unroll
        for (int kp = 0; kp < 16; ++kp) {
            ulonglong2 uA = *(const ulonglong2*)&Usp[kp][b0];
            ulonglong2 uB = *(const ulonglong2*)&Usp[kp][b0 + 2];
            ulonglong2 wA = *(const ulonglong2*)&Wsp[kp][rr0];
            ulonglong2 wB = *(const ulonglong2*)&Wsp[kp][rr0 + 2];
            fma2(a[0][0], wA.x, uA.x); fma2(a[0][1], wA.x, uA.y);
            fma2(a[0][2], wA.x, uB.x); fma2(a[0][3], wA.x, uB.y);
            fma2(a[1][0], wA.y, uA.x); fma2(a[1][1], wA.y, uA.y);
            fma2(a[1][2], wA.y, uB.x); fma2(a[1][3], wA.y, uB.y);
            fma2(a[2][0], wB.x, uA.x); fma2(a[2][1], wB.x, uA.y);
            fma2(a[2][2], wB.x, uB.x); fma2(a[2][3], wB.x, uB.y);
            fma2(a[3][0], wB.y, uA.x); fma2(a[3][1], wB.y, uA.y);
            fma2(a[3][2], wB.y, uB.x); fma2(a[3][3], wB.y, uB.y);
        }
        __syncthreads();
    }
#pragma unroll
    for (int i = 0; i < 4; ++i) {
        int rw = rbase + rr0 + i;
        float bias = cb ? (bih_b[rw] + bhh_b[rw]) : (bih_f[rw] + bhh_f[rw]);
        float o[4];
#pragma unroll
        for (int c = 0; c < 4; ++c) {
            float lo, hi; unpk(a[i][c], lo, hi);
            o[c] = lo + hi + bias;
        }
        *(float4*)&g_P[((size_t)t * R4 + (size_t)(r0 + rr0 + i)) * Bb + b0] =
            make_float4(o[0], o[1], o[2], o[3]);
    }
}

// =====================================================================
// Kernel 2: persistent recurrence. 128 blocks x 256 thr (8 warps).
// warp w -> hidden unit j = g*8+w, 4 gate rows; lane = batch. FFMA2 over k.
// =====================================================================
__global__ void __launch_bounds__(NTHR, 1) rec_kernel(
    const float* __restrict__ whh_f, const float* __restrict__ whh_b,
    const float* __restrict__ wih_f, const float* __restrict__ wih_b)
{
    extern __shared__ char smraw[];
    float* ws   = (float*)smraw;              // [32 rows][512k]  rows = w*4+gate
    u64*   hp   = (u64*)(smraw + 65536);      // [256 kpair][32 b]
    float* rsum = (float*)(smraw + 131072);   // [32]
    float* red  = rsum + 32;                  // [256]

    const int tid  = threadIdx.x;
    const int w    = tid >> 5;
    const int b    = tid & 31;
    const int cell = blockIdx.x >> 6;
    const int g    = blockIdx.x & 63;
    const int j    = g * 8 + w;

    const float* whh = cell ? whh_b : whh_f;
    const float* wih = cell ? wih_b : wih_f;

    // load Whh rows: local row rl = w_*4+gate  <->  global row gate*512 + g*8 + w_
    for (int idx = tid * 4; idx < 32 * 512; idx += NTHR * 4) {
        int rl = idx >> 9, k = idx & 511;
        int grow = (rl & 3) * 512 + g * 8 + (rl >> 2);
        *(float4*)&ws[idx] = *(const float4*)&whh[(size_t)grow * 512 + k];
    }
    {   // rowsums of Wih (sub-step-2 scalar-broadcast input projection)
        int rl = tid & 31, part = tid >> 5;
        int grow = (rl & 3) * 512 + g * 8 + (rl >> 2);
        float s = 0.0f;
        const float* p = &wih[(size_t)grow * 512 + part * 64];
#pragma unroll 4
        for (int k = 0; k < 64; k += 4) {
            float4 v = *(const float4*)&p[k];
            s += v.x + v.y + v.z + v.w;
        }
        red[tid] = s;
    }
    __syncthreads();
    if (tid < 32) {
        float s = 0.0f;
#pragma unroll
        for (int p = 0; p < 8; ++p) s += red[tid + 32 * p];
        rsum[tid] = s;
    }
    __syncthreads();
    float rs[4];
#pragma unroll
    for (int gt = 0; gt < 4; ++gt) rs[gt] = rsum[w * 4 + gt];

    float c = 0.0f;
    const float* wr = ws + (w * 4) * 512;
    volatile unsigned* vbar = &g_bar;
    const bool is_xh = (cell == 1 && j == Hh - 1);

    for (int step = 0; step < 2 * Tt; ++step) {
        const int t = step >> 1, sub = step & 1;
        const int rbuf = step & 1, wbuf = rbuf ^ 1;

        // P prefetch (consumed only after the matvec -> latency hidden)
        float pv[4];
        {
            const float* Pt = g_P + ((size_t)t * R4 + (size_t)cell * 2048) * Bb;
#pragma unroll
            for (int gt = 0; gt < 4; ++gt)
                pv[gt] = Pt[(size_t)(gt * 512 + j) * Bb + b];
        }
        float xh = sub ? g_H[rbuf][1][255][b][1] : 0.0f;

        if (step == 0) {
            for (int i = tid; i < 256 * 32; i += NTHR) hp[i] = 0ULL;
        } else {
            ulonglong2* dst = (ulonglong2*)hp;
            const ulonglong2* src = (const ulonglong2*)&g_H[rbuf][cell][0][0][0];
            for (int i = tid; i < 256 * 32 / 2; i += NTHR) dst[i] = src[i];
        }
        __syncthreads();

        u64 a0 = 0ULL, a1 = 0ULL, a2 = 0ULL, a3 = 0ULL;
        const u64* hpb = hp + b;
#pragma unroll 8
        for (int k = 0; k < 512; k += 4) {
            u64 hA = hpb[(k >> 1) * 32];
            u64 hB = hpb[(k >> 1) * 32 + 32];
            ulonglong2 w0 = *(const ulonglong2*)&wr[0 * 512 + k];
            ulonglong2 w1 = *(const ulonglong2*)&wr[1 * 512 + k];
            ulonglong2 w2 = *(const ulonglong2*)&wr[2 * 512 + k];
            ulonglong2 w3 = *(const ulonglong2*)&wr[3 * 512 + k];
            fma2(a0, w0.x, hA); fma2(a0, w0.y, hB);
            fma2(a1, w1.x, hA); fma2(a1, w1.y, hB);
            fma2(a2, w2.x, hA); fma2(a2, w2.y, hB);
            fma2(a3, w3.x, hA); fma2(a3, w3.y, hB);
        }
        float lo, hi;
        unpk(a0, lo, hi); float iv = lo + hi + pv[0] + xh * rs[0];
        unpk(a1, lo, hi); float fv = lo + hi + pv[1] + xh * rs[1];
        unpk(a2, lo, hi); float gv = lo + hi + pv[2] + xh * rs[2];
        unpk(a3, lo, hi); float ov = lo + hi + pv[3] + xh * rs[3];

        c = fsig(fv) * c + fsig(iv) * ftanh(gv);
        float h2 = fsig(ov) * ftanh(c);
        g_H[wbuf][cell][j >> 1][b][j & 1] = h2;
        if (is_xh) g_XH[sub][t][b] = h2;

        if (step == 2 * Tt - 1) break;
        __threadfence();
        __syncthreads();
        if (tid == 0) {
            atomicAdd(&g_bar, 1u);
            unsigned want = (unsigned)(step + 1) * NBLK;
            while (*vbar < want) __nanosleep(32);
        }
        __syncthreads();
        __threadfence();
    }
}

// =====================================================================
// Kernel 3: out = 1.5*u + 0.5*(xh1 + xh2)
// =====================================================================
__global__ __launch_bounds__(256) void epi_kernel(const float* __restrict__ U,
                                                  float* __restrict__ out)
{
    int idx = blockIdx.x * blockDim.x + threadIdx.x;   // float4 index
    if (idx >= Bb * Tt * Dd / 4) return;
    int t = (idx >> 7) & (Tt - 1);
    int b = idx >> 17;
    float s = 0.5f * (g_XH[0][t][b] + g_XH[1][t][b]);
    float4 u = ((const float4*)U)[idx];
    ((float4*)out)[idx] = make_float4(1.5f * u.x + s, 1.5f * u.y + s,
                                      1.5f * u.z + s, 1.5f * u.w + s);
}

extern "C" void kernel_launch(void* const* d_in, const int* in_sizes, int n_in,
                              void* d_out, int out_size) {
    const float* U     = (const float*)d_in[0];
    const float* wih_f = (const float*)d_in[1];
    const float* whh_f = (const float*)d_in[2];
    const float* bih_f = (const float*)d_in[3];
    const float* bhh_f = (const float*)d_in[4];
    const float* wih_b = (const float*)d_in[5];
    const float* whh_b = (const float*)d_in[6];
    const float* bih_b = (const float*)d_in[7];
    const float* bhh_b = (const float*)d_in[8];
    float* out = (float*)d_out;

    const int smem_sz = 65536 + 65536 + (32 + NTHR) * 4;
    cudaFuncSetAttribute(rec_kernel, cudaFuncAttributeMaxDynamicSharedMemorySize, smem_sz);

    void* bar_addr = nullptr;
    cudaGetSymbolAddress(&bar_addr, g_bar);
    cudaMemsetAsync(bar_addr, 0, sizeof(unsigned), 0);

    pre_kernel<<<dim3(32, Tt), 256>>>(U, wih_f, wih_b, bih_f, bhh_f, bih_b, bhh_b);
    rec_kernel<<<NBLK, NTHR, smem_sz>>>(whh_f, whh_b, wih_f, wih_b);
    epi_kernel<<<(Bb * Tt * Dd / 4 + 255) / 256, 256>>>(U, out);
}

// round 5
// speedup vs baseline: 1.1096x; 1.0867x over previous
#include <cuda_runtime.h>
#include <cstdint>
#include <cstddef>
#include <math.h>

#define Bb 32
#define Tt 1024
#define Dd 512
#define Hh 512
#define R4 4096
#define NBLK 128
#define NTHR 128

__device__ float    g_P[(size_t)Tt * R4 * Bb];   // [t][r][b], r = cell*2048+gate*512+j
__device__ float    g_H[2][2][Hh/4][Bb][4];      // [pp][cell][j/4][b][j&3]
__device__ float    g_XH[2][Tt][Bb];
__device__ unsigned g_bar;

__device__ __forceinline__ float fsig(float x) {
    x = fminf(fmaxf(x, -30.0f), 30.0f);
    return __fdividef(1.0f, 1.0f + __expf(-x));
}
__device__ __forceinline__ float ftanh(float x) {
    x = fminf(fmaxf(x, -15.0f), 15.0f);
    float e = __expf(2.0f * x);
    return __fdividef(e - 1.0f, e + 1.0f);
}
__device__ __forceinline__ float4 ldcg4(const float4* p) {
    float4 v;
    asm volatile("ld.global.cg.v4.f32 {%0,%1,%2,%3},[%4];"
                 : "=f"(v.x), "=f"(v.y), "=f"(v.z), "=f"(v.w) : "l"(p));
    return v;
}
__device__ __forceinline__ void stcg2(float2* p, float2 v) {
    asm volatile("st.global.cg.v2.f32 [%0],{%1,%2};" :: "l"(p), "f"(v.x), "f"(v.y));
}
__device__ __forceinline__ float ldcg1(const float* p) {
    float v; asm volatile("ld.global.cg.f32 %0,[%1];" : "=f"(v) : "l"(p)); return v;
}

// =====================================================================
// Kernel 1: P[t][r][b] = sum_d U[b][t][d]*Wih[r][d] + bih[r] + bhh[r]
// =====================================================================
__global__ __launch_bounds__(256) void pre_kernel(
    const float* __restrict__ U,
    const float* __restrict__ wih_f, const float* __restrict__ wih_b,
    const float* __restrict__ bih_f, const float* __restrict__ bhh_f,
    const float* __restrict__ bih_b, const float* __restrict__ bhh_b)
{
    __shared__ float Us[32][36];
    __shared__ float Ws[32][132];

    const int t  = blockIdx.y;
    const int r0 = blockIdx.x * 128;
    const int cb = (r0 >= 2048);
    const float* wih = cb ? wih_b : wih_f;
    const int rbase = r0 - cb * 2048;

    const int tid = threadIdx.x;
    const int b0  = (tid & 7) * 4;
    const int rr0 = ((tid >> 3) & 31) * 4;

    float acc[4][4];
#pragma unroll
    for (int i = 0; i < 4; ++i)
#pragma unroll
        for (int j = 0; j < 4; ++j) acc[i][j] = 0.0f;

    for (int kt = 0; kt < 16; ++kt) {
        const int k0 = kt * 32;
        {
            int bb = tid >> 3, kq = tid & 7;
            float4 v = *(const float4*)&U[(size_t)bb * (Tt * Dd) + (size_t)t * Dd + k0 + kq * 4];
            Us[kq * 4 + 0][bb] = v.x; Us[kq * 4 + 1][bb] = v.y;
            Us[kq * 4 + 2][bb] = v.z; Us[kq * 4 + 3][bb] = v.w;
        }
#pragma unroll
        for (int ii = 0; ii < 4; ++ii) {
            int rr = (tid >> 3) + 32 * ii, kq = tid & 7;
            float4 v = *(const float4*)&wih[(size_t)(rbase + rr) * Dd + k0 + kq * 4];
            Ws[kq * 4 + 0][rr] = v.x; Ws[kq * 4 + 1][rr] = v.y;
            Ws[kq * 4 + 2][rr] = v.z; Ws[kq * 4 + 3][rr] = v.w;
        }
        __syncthreads();
#pragma unroll
        for (int k = 0; k < 32; ++k) {
            float4 ub = *(const float4*)&Us[k][b0];
            float4 wr = *(const float4*)&Ws[k][rr0];
            acc[0][0] += wr.x*ub.x; acc[0][1] += wr.x*ub.y; acc[0][2] += wr.x*ub.z; acc[0][3] += wr.x*ub.w;
            acc[1][0] += wr.y*ub.x; acc[1][1] += wr.y*ub.y; acc[1][2] += wr.y*ub.z; acc[1][3] += wr.y*ub.w;
            acc[2][0] += wr.z*ub.x; acc[2][1] += wr.z*ub.y; acc[2][2] += wr.z*ub.z; acc[2][3] += wr.z*ub.w;
            acc[3][0] += wr.w*ub.x; acc[3][1] += wr.w*ub.y; acc[3][2] += wr.w*ub.z; acc[3][3] += wr.w*ub.w;
        }
        __syncthreads();
    }
#pragma unroll
    for (int i = 0; i < 4; ++i) {
        int rw = rbase + rr0 + i;
        float bias = cb ? (bih_b[rw] + bhh_b[rw]) : (bih_f[rw] + bhh_f[rw]);
        float4 o = make_float4(acc[i][0]+bias, acc[i][1]+bias, acc[i][2]+bias, acc[i][3]+bias);
        *(float4*)&g_P[((size_t)t * R4 + (size_t)(r0 + rr0 + i)) * Bb + b0] = o;
    }
}

// =====================================================================
// Kernel 2: persistent recurrence. 128 blocks x 128 thr (4 warps).
// warp w -> units jA=g*8+2w, jB=jA+1 (8 gate rows); lane = batch.
// =====================================================================
__global__ void __launch_bounds__(NTHR, 1) rec_kernel(
    const float* __restrict__ whh_f, const float* __restrict__ whh_b,
    const float* __restrict__ wih_f, const float* __restrict__ wih_b)
{
    extern __shared__ char smraw[];
    float*  ws   = (float*)smraw;               // [32 rows][512] rows: w*8 + u*4 + gate
    float4* hs   = (float4*)(smraw + 65536);    // [128 kquad][32 b]
    float*  rsum = (float*)(smraw + 131072);    // [32]
    float*  red  = rsum + 32;                   // [128]

    const int tid  = threadIdx.x;
    const int w    = tid >> 5;
    const int b    = tid & 31;
    const int cell = blockIdx.x >> 6;
    const int g    = blockIdx.x & 63;
    const int jA   = g * 8 + 2 * w;             // units jA, jA+1

    const float* whh = cell ? whh_b : whh_f;
    const float* wih = cell ? wih_b : wih_f;

    // Whh rows -> SMEM: rl = w_*8 + u*4 + gate <-> grow = gate*512 + g*8 + 2w_ + u
    for (int idx = tid * 4; idx < 32 * 512; idx += NTHR * 4) {
        int rl = idx >> 9, k = idx & 511;
        int w_ = rl >> 3, q = rl & 7, u = q >> 2, gate = q & 3;
        int grow = gate * 512 + g * 8 + 2 * w_ + u;
        *(float4*)&ws[idx] = *(const float4*)&whh[(size_t)grow * 512 + k];
    }
    {   // rowsums of Wih
        int rl = tid & 31, part = tid >> 5;     // 4 parts x 128 k
        int w_ = rl >> 3, q = rl & 7, u = q >> 2, gate = q & 3;
        int grow = gate * 512 + g * 8 + 2 * w_ + u;
        float s = 0.0f;
        const float* p = &wih[(size_t)grow * 512 + part * 128];
#pragma unroll 4
        for (int k = 0; k < 128; k += 4) {
            float4 v = *(const float4*)&p[k];
            s += v.x + v.y + v.z + v.w;
        }
        red[tid] = s;
    }
    __syncthreads();
    if (tid < 32) rsum[tid] = red[tid] + red[tid + 32] + red[tid + 64] + red[tid + 96];
    __syncthreads();
    float rs[8];
#pragma unroll
    for (int q = 0; q < 8; ++q) rs[q] = rsum[w * 8 + q];

    float cst[2] = {0.0f, 0.0f};
    const float4* wr4 = (const float4*)(ws + (w * 8) * 512);   // [q*128 + kq]
    volatile unsigned* vbar = &g_bar;
    const bool is_xh = (cell == 1 && jA + 1 == Hh - 1);

    for (int step = 0; step < 2 * Tt; ++step) {
        const int t = step >> 1, sub = step & 1;
        const int rbuf = step & 1, wbuf = rbuf ^ 1;

        // P prefetch (hidden behind h copy + matvec)
        float pv[8];
        {
            const float* Pt = g_P + ((size_t)t * R4 + (size_t)cell * 2048) * Bb;
#pragma unroll
            for (int q = 0; q < 8; ++q) {
                int u = q >> 2, gate = q & 3;
                pv[q] = Pt[(size_t)(gate * 512 + jA + u) * Bb + b];
            }
        }
        float xh = sub ? ldcg1(&g_H[rbuf][1][(Hh - 1) >> 2][b][3]) : 0.0f;

        if (step == 0) {
            float4 z = make_float4(0.f, 0.f, 0.f, 0.f);
            for (int i = tid; i < 128 * 32; i += NTHR) hs[i] = z;
        } else {
            const float4* src = (const float4*)&g_H[rbuf][cell][0][0][0];
            for (int i = tid; i < 128 * 32; i += NTHR) hs[i] = ldcg4(&src[i]);
        }
        __syncthreads();

        float acc[8];
#pragma unroll
        for (int q = 0; q < 8; ++q) acc[q] = 0.0f;
        const float4* hb = hs + b;
#pragma unroll 4
        for (int kq = 0; kq < 128; ++kq) {
            float4 hv = hb[kq * 32];
#pragma unroll
            for (int q = 0; q < 8; ++q) {
                float4 wv = wr4[q * 128 + kq];
                acc[q] += wv.x * hv.x;
                acc[q] += wv.y * hv.y;
                acc[q] += wv.z * hv.z;
                acc[q] += wv.w * hv.w;
            }
        }

        float h2v[2];
#pragma unroll
        for (int u = 0; u < 2; ++u) {
            float iv = acc[u*4+0] + pv[u*4+0] + xh * rs[u*4+0];
            float fv = acc[u*4+1] + pv[u*4+1] + xh * rs[u*4+1];
            float gv = acc[u*4+2] + pv[u*4+2] + xh * rs[u*4+2];
            float ov = acc[u*4+3] + pv[u*4+3] + xh * rs[u*4+3];
            cst[u] = fsig(fv) * cst[u] + fsig(iv) * ftanh(gv);
            h2v[u] = fsig(ov) * ftanh(cst[u]);
        }
        stcg2((float2*)&g_H[wbuf][cell][jA >> 2][b][jA & 3],
              make_float2(h2v[0], h2v[1]));
        if (is_xh) g_XH[sub][t][b] = h2v[1];

        if (step == 2 * Tt - 1) break;
        __threadfence();
        __syncthreads();
        if (tid == 0) {
            atomicAdd(&g_bar, 1u);
            unsigned want = (unsigned)(step + 1) * NBLK;
            while (*vbar < want) { }
        }
        __syncthreads();
    }
}

// =====================================================================
// Kernel 3: out = 1.5*u + 0.5*(xh1 + xh2)
// =====================================================================
__global__ __launch_bounds__(256) void epi_kernel(const float* __restrict__ U,
                                                  float* __restrict__ out)
{
    int idx = blockIdx.x * blockDim.x + threadIdx.x;
    if (idx >= Bb * Tt * Dd / 4) return;
    int t = (idx >> 7) & (Tt - 1);
    int b = idx >> 17;
    float s = 0.5f * (g_XH[0][t][b] + g_XH[1][t][b]);
    float4 u = ((const float4*)U)[idx];
    ((float4*)out)[idx] = make_float4(1.5f * u.x + s, 1.5f * u.y + s,
                                      1.5f * u.z + s, 1.5f * u.w + s);
}

extern "C" void kernel_launch(void* const* d_in, const int* in_sizes, int n_in,
                              void* d_out, int out_size) {
    const float* U     = (const float*)d_in[0];
    const float* wih_f = (const float*)d_in[1];
    const float* whh_f = (const float*)d_in[2];
    const float* bih_f = (const float*)d_in[3];
    const float* bhh_f = (const float*)d_in[4];
    const float* wih_b = (const float*)d_in[5];
    const float* whh_b = (const float*)d_in[6];
    const float* bih_b = (const float*)d_in[7];
    const float* bhh_b = (const float*)d_in[8];
    float* out = (float*)d_out;

    const int smem_sz = 65536 + 65536 + (32 + NTHR) * 4;
    cudaFuncSetAttribute(rec_kernel, cudaFuncAttributeMaxDynamicSharedMemorySize, smem_sz);

    void* bar_addr = nullptr;
    cudaGetSymbolAddress(&bar_addr, g_bar);
    cudaMemsetAsync(bar_addr, 0, sizeof(unsigned), 0);

    pre_kernel<<<dim3(32, Tt), 256>>>(U, wih_f, wih_b, bih_f, bhh_f, bih_b, bhh_b);
    rec_kernel<<<NBLK, NTHR, smem_sz>>>(whh_f, whh_b, wih_f, wih_b);
    epi_kernel<<<(Bb * Tt * Dd / 4 + 255) / 256, 256>>>(U, out);
}

// round 6
// speedup vs baseline: 1.2709x; 1.1453x over previous
#include <cuda_runtime.h>
#include <cstdint>
#include <cstddef>
#include <math.h>

#define Bb 32
#define Tt 1024
#define Dd 512
#define Hh 512
#define R4 4096
#define NBLK 128
#define NTHR 256

__device__ float    g_P[(size_t)Tt * R4 * Bb];   // [t][r][b], r = cell*2048+gate*512+j
__device__ float    g_H[2][2][Hh/4][Bb][4];      // [pp][cell][j/4][b][j&3]
__device__ float    g_XH[2][Tt][Bb];
__device__ unsigned g_bar;

__device__ __forceinline__ float fsig(float x) {
    x = fminf(fmaxf(x, -30.0f), 30.0f);
    return __fdividef(1.0f, 1.0f + __expf(-x));
}
__device__ __forceinline__ float ftanh(float x) {
    x = fminf(fmaxf(x, -15.0f), 15.0f);
    float e = __expf(2.0f * x);
    return __fdividef(e - 1.0f, e + 1.0f);
}
__device__ __forceinline__ float4 ldcg4(const float4* p) {
    float4 v;
    asm volatile("ld.global.cg.v4.f32 {%0,%1,%2,%3},[%4];"
                 : "=f"(v.x), "=f"(v.y), "=f"(v.z), "=f"(v.w) : "l"(p));
    return v;
}
__device__ __forceinline__ void stcg2(float2* p, float2 v) {
    asm volatile("st.global.cg.v2.f32 [%0],{%1,%2};" :: "l"(p), "f"(v.x), "f"(v.y));
}
__device__ __forceinline__ float ldcg1(const float* p) {
    float v; asm volatile("ld.global.cg.f32 %0,[%1];" : "=f"(v) : "l"(p)); return v;
}

// =====================================================================
// Kernel 1: P[t][r][b] = sum_d U[b][t][d]*Wih[r][d] + bih[r] + bhh[r]
// (measured at ~fp32 FFMA roofline — unchanged from best version)
// =====================================================================
__global__ __launch_bounds__(256) void pre_kernel(
    const float* __restrict__ U,
    const float* __restrict__ wih_f, const float* __restrict__ wih_b,
    const float* __restrict__ bih_f, const float* __restrict__ bhh_f,
    const float* __restrict__ bih_b, const float* __restrict__ bhh_b)
{
    __shared__ float Us[32][36];
    __shared__ float Ws[32][132];

    const int t  = blockIdx.y;
    const int r0 = blockIdx.x * 128;
    const int cb = (r0 >= 2048);
    const float* wih = cb ? wih_b : wih_f;
    const int rbase = r0 - cb * 2048;

    const int tid = threadIdx.x;
    const int b0  = (tid & 7) * 4;
    const int rr0 = ((tid >> 3) & 31) * 4;

    float acc[4][4];
#pragma unroll
    for (int i = 0; i < 4; ++i)
#pragma unroll
        for (int j = 0; j < 4; ++j) acc[i][j] = 0.0f;

    for (int kt = 0; kt < 16; ++kt) {
        const int k0 = kt * 32;
        {
            int bb = tid >> 3, kq = tid & 7;
            float4 v = *(const float4*)&U[(size_t)bb * (Tt * Dd) + (size_t)t * Dd + k0 + kq * 4];
            Us[kq * 4 + 0][bb] = v.x; Us[kq * 4 + 1][bb] = v.y;
            Us[kq * 4 + 2][bb] = v.z; Us[kq * 4 + 3][bb] = v.w;
        }
#pragma unroll
        for (int ii = 0; ii < 4; ++ii) {
            int rr = (tid >> 3) + 32 * ii, kq = tid & 7;
            float4 v = *(const float4*)&wih[(size_t)(rbase + rr) * Dd + k0 + kq * 4];
            Ws[kq * 4 + 0][rr] = v.x; Ws[kq * 4 + 1][rr] = v.y;
            Ws[kq * 4 + 2][rr] = v.z; Ws[kq * 4 + 3][rr] = v.w;
        }
        __syncthreads();
#pragma unroll
        for (int k = 0; k < 32; ++k) {
            float4 ub = *(const float4*)&Us[k][b0];
            float4 wr = *(const float4*)&Ws[k][rr0];
            acc[0][0] += wr.x*ub.x; acc[0][1] += wr.x*ub.y; acc[0][2] += wr.x*ub.z; acc[0][3] += wr.x*ub.w;
            acc[1][0] += wr.y*ub.x; acc[1][1] += wr.y*ub.y; acc[1][2] += wr.y*ub.z; acc[1][3] += wr.y*ub.w;
            acc[2][0] += wr.z*ub.x; acc[2][1] += wr.z*ub.y; acc[2][2] += wr.z*ub.z; acc[2][3] += wr.z*ub.w;
            acc[3][0] += wr.w*ub.x; acc[3][1] += wr.w*ub.y; acc[3][2] += wr.w*ub.z; acc[3][3] += wr.w*ub.w;
        }
        __syncthreads();
    }
#pragma unroll
    for (int i = 0; i < 4; ++i) {
        int rw = rbase + rr0 + i;
        float bias = cb ? (bih_b[rw] + bhh_b[rw]) : (bih_f[rw] + bhh_f[rw]);
        float4 o = make_float4(acc[i][0]+bias, acc[i][1]+bias, acc[i][2]+bias, acc[i][3]+bias);
        *(float4*)&g_P[((size_t)t * R4 + (size_t)(r0 + rr0 + i)) * Bb + b0] = o;
    }
}

// =====================================================================
// Kernel 2: persistent recurrence. 128 blocks x 256 thr (8 warps).
// warp w: p=w&3 -> units jA=g*8+2p, jA+1 (8 gate rows); kh=w>>2 -> k-half.
// lane = batch. Partials reduced in SMEM; epilogue on warps 0-3.
// =====================================================================
__global__ void __launch_bounds__(NTHR, 1) rec_kernel(
    const float* __restrict__ whh_f, const float* __restrict__ whh_b,
    const float* __restrict__ wih_f, const float* __restrict__ wih_b)
{
    extern __shared__ char smraw[];
    float*  ws   = (float*)smraw;                 // [32 rows][512]  row = p*8+u*4+gate
    float4* hs   = (float4*)(smraw + 65536);      // [128 kq][32 b]
    float*  redA = (float*)(smraw + 131072);      // [8 w][8 q][32 b]
    float*  rsum = redA + 8*8*32;                 // [32]
    float*  red  = rsum + 32;                     // [256]

    const int tid  = threadIdx.x;
    const int w    = tid >> 5;
    const int p    = w & 3;
    const int kh   = w >> 2;
    const int b    = tid & 31;
    const int cell = blockIdx.x >> 6;
    const int g    = blockIdx.x & 63;
    const int jA   = g * 8 + 2 * p;

    const float* whh = cell ? whh_b : whh_f;
    const float* wih = cell ? wih_b : wih_f;

    for (int idx = tid * 4; idx < 32 * 512; idx += NTHR * 4) {
        int rl = idx >> 9, k = idx & 511;
        int p_ = rl >> 3, q = rl & 7, u = q >> 2, gate = q & 3;
        int grow = gate * 512 + g * 8 + 2 * p_ + u;
        *(float4*)&ws[idx] = *(const float4*)&whh[(size_t)grow * 512 + k];
    }
    {   // rowsums of Wih (sub-step-2 scalar-broadcast projection)
        int rl = tid & 31, part = tid >> 5;      // 8 parts x 64 k
        int p_ = rl >> 3, q = rl & 7, u = q >> 2, gate = q & 3;
        int grow = gate * 512 + g * 8 + 2 * p_ + u;
        float s = 0.0f;
        const float* pp = &wih[(size_t)grow * 512 + part * 64];
#pragma unroll 4
        for (int k = 0; k < 64; k += 4) {
            float4 v = *(const float4*)&pp[k];
            s += v.x + v.y + v.z + v.w;
        }
        red[tid] = s;
    }
    __syncthreads();
    if (tid < 32) {
        float s = 0.0f;
#pragma unroll
        for (int q = 0; q < 8; ++q) s += red[tid + 32 * q];
        rsum[tid] = s;
    }
    __syncthreads();
    float rs[8];
#pragma unroll
    for (int q = 0; q < 8; ++q) rs[q] = rsum[p * 8 + q];

    float cst[2] = {0.0f, 0.0f};
    const float4* wr4 = (const float4*)(ws + (p * 8) * 512);  // [q*128 + kq]
    const bool is_xh = (cell == 1 && jA + 1 == Hh - 1);

    for (int step = 0; step < 2 * Tt; ++step) {
        const int t = step >> 1, sub = step & 1;
        const int rbuf = step & 1, wbuf = rbuf ^ 1;

        // prefetch P + xh (DRAM/L2 latency hides under h copy + matvec)
        float pv[8];
        if (kh == 0) {
            const float* Pt = g_P + ((size_t)t * R4 + (size_t)cell * 2048) * Bb;
#pragma unroll
            for (int q = 0; q < 8; ++q) {
                int u = q >> 2, gate = q & 3;
                pv[q] = Pt[(size_t)(gate * 512 + jA + u) * Bb + b];
            }
        }
        float xh = (sub && kh == 0) ? ldcg1(&g_H[rbuf][1][(Hh - 1) >> 2][b][3]) : 0.0f;

        if (step == 0) {
            float4 z = make_float4(0.f, 0.f, 0.f, 0.f);
            for (int i = tid; i < 128 * 32; i += NTHR) hs[i] = z;
        } else {
            const float4* src = (const float4*)&g_H[rbuf][cell][0][0][0];
            for (int i = tid; i < 128 * 32; i += NTHR) hs[i] = ldcg4(&src[i]);
        }
        __syncthreads();

        // half-k matvec for this warp
        float acc[8];
#pragma unroll
        for (int q = 0; q < 8; ++q) acc[q] = 0.0f;
        const float4* hb = hs + b;
#pragma unroll 4
        for (int kq = kh * 64; kq < kh * 64 + 64; ++kq) {
            float4 hv = hb[kq * 32];
#pragma unroll
            for (int q = 0; q < 8; ++q) {
                float4 wv = wr4[q * 128 + kq];
                acc[q] += wv.x * hv.x;
                acc[q] += wv.y * hv.y;
                acc[q] += wv.z * hv.z;
                acc[q] += wv.w * hv.w;
            }
        }
#pragma unroll
        for (int q = 0; q < 8; ++q) redA[(w * 8 + q) * 32 + b] = acc[q];
        __syncthreads();

        if (kh == 0) {
            float h2v[2];
#pragma unroll
            for (int u = 0; u < 2; ++u) {
#pragma unroll
                for (int q = 0; q < 4; ++q) {
                    int qq = u * 4 + q;
                    acc[qq] += redA[((w + 4) * 8 + qq) * 32 + b];
                    acc[qq] += pv[qq] + xh * rs[qq];
                }
                float iv = acc[u*4+0], fv = acc[u*4+1], gv = acc[u*4+2], ov = acc[u*4+3];
                cst[u] = fsig(fv) * cst[u] + fsig(iv) * ftanh(gv);
                h2v[u] = fsig(ov) * ftanh(cst[u]);
            }
            stcg2((float2*)&g_H[wbuf][cell][jA >> 2][b][jA & 3],
                  make_float2(h2v[0], h2v[1]));
            if (is_xh) g_XH[sub][t][b] = h2v[1];
        }

        if (step == 2 * Tt - 1) break;
        __syncthreads();   // all stores done block-wide (HB for tid0's fence)
        if (tid == 0) {
            asm volatile("membar.gl;" ::: "memory");
            atomicAdd(&g_bar, 1u);
            unsigned want = (unsigned)(step + 1) * NBLK;
            unsigned v;
            do {
                asm volatile("ld.acquire.gpu.global.u32 %0,[%1];" : "=r"(v) : "l"(&g_bar));
            } while (v < want);
        }
        __syncthreads();
    }
}

// =====================================================================
// Kernel 3: out = 1.5*u + 0.5*(xh1 + xh2)
// =====================================================================
__global__ __launch_bounds__(256) void epi_kernel(const float* __restrict__ U,
                                                  float* __restrict__ out)
{
    int idx = blockIdx.x * blockDim.x + threadIdx.x;
    if (idx >= Bb * Tt * Dd / 4) return;
    int t = (idx >> 7) & (Tt - 1);
    int b = idx >> 17;
    float s = 0.5f * (g_XH[0][t][b] + g_XH[1][t][b]);
    float4 u = ((const float4*)U)[idx];
    ((float4*)out)[idx] = make_float4(1.5f * u.x + s, 1.5f * u.y + s,
                                      1.5f * u.z + s, 1.5f * u.w + s);
}

extern "C" void kernel_launch(void* const* d_in, const int* in_sizes, int n_in,
                              void* d_out, int out_size) {
    const float* U     = (const float*)d_in[0];
    const float* wih_f = (const float*)d_in[1];
    const float* whh_f = (const float*)d_in[2];
    const float* bih_f = (const float*)d_in[3];
    const float* bhh_f = (const float*)d_in[4];
    const float* wih_b = (const float*)d_in[5];
    const float* whh_b = (const float*)d_in[6];
    const float* bih_b = (const float*)d_in[7];
    const float* bhh_b = (const float*)d_in[8];
    float* out = (float*)d_out;

    const int smem_sz = 65536 + 65536 + (8*8*32 + 32 + NTHR) * 4;
    cudaFuncSetAttribute(rec_kernel, cudaFuncAttributeMaxDynamicSharedMemorySize, smem_sz);

    void* bar_addr = nullptr;
    cudaGetSymbolAddress(&bar_addr, g_bar);
    cudaMemsetAsync(bar_addr, 0, sizeof(unsigned), 0);

    pre_kernel<<<dim3(32, Tt), 256>>>(U, wih_f, wih_b, bih_f, bhh_f, bih_b, bhh_b);
    rec_kernel<<<NBLK, NTHR, smem_sz>>>(whh_f, whh_b, wih_f, wih_b);
    epi_kernel<<<(Bb * Tt * Dd / 4 + 255) / 256, 256>>>(U, out);
}

// round 8
// speedup vs baseline: 1.2748x; 1.0031x over previous
#include <cuda_runtime.h>
#include <cstdint>
#include <cstddef>
#include <math.h>

#define Bb 32
#define Tt 1024
#define Dd 512
#define Hh 512
#define R4 4096
#define NBLK 128
#define NTHR 256

__device__ float    g_P[(size_t)Tt * R4 * Bb];   // [t][r][b], r = cell*2048+gate*512+j
__device__ float    g_H[2][2][Hh/4][Bb][4];      // [pp][cell][j/4][b][j&3]
__device__ float    g_XH[2][Tt][Bb];
__device__ unsigned g_bar;

__device__ __forceinline__ float fsig(float x) {
    x = fminf(fmaxf(x, -30.0f), 30.0f);
    return __fdividef(1.0f, 1.0f + __expf(-x));
}
__device__ __forceinline__ float ftanh(float x) {
    x = fminf(fmaxf(x, -15.0f), 15.0f);
    float e = __expf(2.0f * x);
    return __fdividef(e - 1.0f, e + 1.0f);
}
__device__ __forceinline__ float4 ldcg4(const float4* p) {
    float4 v;
    asm volatile("ld.global.cg.v4.f32 {%0,%1,%2,%3},[%4];"
                 : "=f"(v.x), "=f"(v.y), "=f"(v.z), "=f"(v.w) : "l"(p));
    return v;
}
__device__ __forceinline__ void stcg2(float2* p, float2 v) {
    asm volatile("st.global.cg.v2.f32 [%0],{%1,%2};" :: "l"(p), "f"(v.x), "f"(v.y));
}
__device__ __forceinline__ float ldcg1(const float* p) {
    float v; asm volatile("ld.global.cg.f32 %0,[%1];" : "=f"(v) : "l"(p)); return v;
}

// =====================================================================
// Kernel 1: P[t][r][b] = sum_d U[b][t][d]*Wih[r][d] + bih[r] + bhh[r]
// Double-buffered K-tiles: LDG prefetch into regs overlaps compute.
// =====================================================================
__global__ __launch_bounds__(256) void pre_kernel(
    const float* __restrict__ U,
    const float* __restrict__ wih_f, const float* __restrict__ wih_b,
    const float* __restrict__ bih_f, const float* __restrict__ bhh_f,
    const float* __restrict__ bih_b, const float* __restrict__ bhh_b)
{
    __shared__ float Us[2][32][36];
    __shared__ float Ws[2][32][132];

    const int t  = blockIdx.y;
    const int r0 = blockIdx.x * 128;
    const int cb = (r0 >= 2048);
    const float* wih = cb ? wih_b : wih_f;
    const int rbase = r0 - cb * 2048;

    const int tid = threadIdx.x;
    const int b0  = (tid & 7) * 4;
    const int rr0 = ((tid >> 3) & 31) * 4;
    const int bb  = tid >> 3;          // 0..31  (U row)
    const int kq  = tid & 7;           // 0..7   (k-quad within tile)

    const float* Ubase = &U[(size_t)bb * (Tt * Dd) + (size_t)t * Dd + kq * 4];
    const float* Wbase = &wih[(size_t)(rbase + (tid >> 3)) * Dd + kq * 4];

    float acc[4][4];
#pragma unroll
    for (int i = 0; i < 4; ++i)
#pragma unroll
        for (int j = 0; j < 4; ++j) acc[i][j] = 0.0f;

    // prologue: load chunk 0, stage into buf 0
    float4 pu = *(const float4*)Ubase;
    float4 pw0 = *(const float4*)&Wbase[(size_t)(32 * 0) * Dd];
    float4 pw1 = *(const float4*)&Wbase[(size_t)(32 * 1) * Dd];
    float4 pw2 = *(const float4*)&Wbase[(size_t)(32 * 2) * Dd];
    float4 pw3 = *(const float4*)&Wbase[(size_t)(32 * 3) * Dd];
    {
        Us[0][kq*4+0][bb] = pu.x; Us[0][kq*4+1][bb] = pu.y;
        Us[0][kq*4+2][bb] = pu.z; Us[0][kq*4+3][bb] = pu.w;
        int rr = tid >> 3;
        Ws[0][kq*4+0][rr+ 0] = pw0.x; Ws[0][kq*4+1][rr+ 0] = pw0.y;
        Ws[0][kq*4+2][rr+ 0] = pw0.z; Ws[0][kq*4+3][rr+ 0] = pw0.w;
        Ws[0][kq*4+0][rr+32] = pw1.x; Ws[0][kq*4+1][rr+32] = pw1.y;
        Ws[0][kq*4+2][rr+32] = pw1.z; Ws[0][kq*4+3][rr+32] = pw1.w;
        Ws[0][kq*4+0][rr+64] = pw2.x; Ws[0][kq*4+1][rr+64] = pw2.y;
        Ws[0][kq*4+2][rr+64] = pw2.z; Ws[0][kq*4+3][rr+64] = pw2.w;
        Ws[0][kq*4+0][rr+96] = pw3.x; Ws[0][kq*4+1][rr+96] = pw3.y;
        Ws[0][kq*4+2][rr+96] = pw3.z; Ws[0][kq*4+3][rr+96] = pw3.w;
    }
    __syncthreads();

    for (int kt = 0; kt < 16; ++kt) {
        const int cur = kt & 1;
        // prefetch next chunk into regs (latency hides under compute below)
        if (kt < 15) {
            const int k1 = (kt + 1) * 32;
            pu  = *(const float4*)&Ubase[k1];
            pw0 = *(const float4*)&Wbase[(size_t)(32 * 0) * Dd + k1];
            pw1 = *(const float4*)&Wbase[(size_t)(32 * 1) * Dd + k1];
            pw2 = *(const float4*)&Wbase[(size_t)(32 * 2) * Dd + k1];
            pw3 = *(const float4*)&Wbase[(size_t)(32 * 3) * Dd + k1];
        }
#pragma unroll
        for (int k = 0; k < 32; ++k) {
            float4 ub = *(const float4*)&Us[cur][k][b0];
            float4 wr = *(const float4*)&Ws[cur][k][rr0];
            acc[0][0] += wr.x*ub.x; acc[0][1] += wr.x*ub.y; acc[0][2] += wr.x*ub.z; acc[0][3] += wr.x*ub.w;
            acc[1][0] += wr.y*ub.x; acc[1][1] += wr.y*ub.y; acc[1][2] += wr.y*ub.z; acc[1][3] += wr.y*ub.w;
            acc[2][0] += wr.z*ub.x; acc[2][1] += wr.z*ub.y; acc[2][2] += wr.z*ub.z; acc[2][3] += wr.z*ub.w;
            acc[3][0] += wr.w*ub.x; acc[3][1] += wr.w*ub.y; acc[3][2] += wr.w*ub.z; acc[3][3] += wr.w*ub.w;
        }
        if (kt < 15) {
            const int nxt = cur ^ 1;
            Us[nxt][kq*4+0][bb] = pu.x; Us[nxt][kq*4+1][bb] = pu.y;
            Us[nxt][kq*4+2][bb] = pu.z; Us[nxt][kq*4+3][bb] = pu.w;
            int rr = tid >> 3;
            Ws[nxt][kq*4+0][rr+ 0] = pw0.x; Ws[nxt][kq*4+1][rr+ 0] = pw0.y;
            Ws[nxt][kq*4+2][rr+ 0] = pw0.z; Ws[nxt][kq*4+3][rr+ 0] = pw0.w;
            Ws[nxt][kq*4+0][rr+32] = pw1.x; Ws[nxt][kq*4+1][rr+32] = pw1.y;
            Ws[nxt][kq*4+2][rr+32] = pw1.z; Ws[nxt][kq*4+3][rr+32] = pw1.w;
            Ws[nxt][kq*4+0][rr+64] = pw2.x; Ws[nxt][kq*4+1][rr+64] = pw2.y;
            Ws[nxt][kq*4+2][rr+64] = pw2.z; Ws[nxt][kq*4+3][rr+64] = pw2.w;
            Ws[nxt][kq*4+0][rr+96] = pw3.x; Ws[nxt][kq*4+1][rr+96] = pw3.y;
            Ws[nxt][kq*4+2][rr+96] = pw3.z; Ws[nxt][kq*4+3][rr+96] = pw3.w;
            __syncthreads();
        }
    }
#pragma unroll
    for (int i = 0; i < 4; ++i) {
        int rw = rbase + rr0 + i;
        float bias = cb ? (bih_b[rw] + bhh_b[rw]) : (bih_f[rw] + bhh_f[rw]);
        float4 o = make_float4(acc[i][0]+bias, acc[i][1]+bias, acc[i][2]+bias, acc[i][3]+bias);
        *(float4*)&g_P[((size_t)t * R4 + (size_t)(r0 + rr0 + i)) * Bb + b0] = o;
    }
}

// =====================================================================
// Kernel 2: persistent recurrence (unchanged from R5 — near its floor).
// =====================================================================
__global__ void __launch_bounds__(NTHR, 1) rec_kernel(
    const float* __restrict__ whh_f, const float* __restrict__ whh_b,
    const float* __restrict__ wih_f, const float* __restrict__ wih_b)
{
    extern __shared__ char smraw[];
    float*  ws   = (float*)smraw;                 // [32 rows][512]  row = p*8+u*4+gate
    float4* hs   = (float4*)(smraw + 65536);      // [128 kq][32 b]
    float*  redA = (float*)(smraw + 131072);      // [8 w][8 q][32 b]
    float*  rsum = redA + 8*8*32;                 // [32]
    float*  red  = rsum + 32;                     // [256]

    const int tid  = threadIdx.x;
    const int w    = tid >> 5;
    const int p    = w & 3;
    const int kh   = w >> 2;
    const int b    = tid & 31;
    const int cell = blockIdx.x >> 6;
    const int g    = blockIdx.x & 63;
    const int jA   = g * 8 + 2 * p;

    const float* whh = cell ? whh_b : whh_f;
    const float* wih = cell ? wih_b : wih_f;

    for (int idx = tid * 4; idx < 32 * 512; idx += NTHR * 4) {
        int rl = idx >> 9, k = idx & 511;
        int p_ = rl >> 3, q = rl & 7, u = q >> 2, gate = q & 3;
        int grow = gate * 512 + g * 8 + 2 * p_ + u;
        *(float4*)&ws[idx] = *(const float4*)&whh[(size_t)grow * 512 + k];
    }
    {   // rowsums of Wih (sub-step-2 scalar-broadcast projection)
        int rl = tid & 31, part = tid >> 5;
        int p_ = rl >> 3, q = rl & 7, u = q >> 2, gate = q & 3;
        int grow = gate * 512 + g * 8 + 2 * p_ + u;
        float s = 0.0f;
        const float* pp = &wih[(size_t)grow * 512 + part * 64];
#pragma unroll 4
        for (int k = 0; k < 64; k += 4) {
            float4 v = *(const float4*)&pp[k];
            s += v.x + v.y + v.z + v.w;
        }
        red[tid] = s;
    }
    __syncthreads();
    if (tid < 32) {
        float s = 0.0f;
#pragma unroll
        for (int q = 0; q < 8; ++q) s += red[tid + 32 * q];
        rsum[tid] = s;
    }
    __syncthreads();
    float rs[8];
#pragma unroll
    for (int q = 0; q < 8; ++q) rs[q] = rsum[p * 8 + q];

    float cst[2] = {0.0f, 0.0f};
    const float4* wr4 = (const float4*)(ws + (p * 8) * 512);
    const bool is_xh = (cell == 1 && jA + 1 == Hh - 1);

    for (int step = 0; step < 2 * Tt; ++step) {
        const int t = step >> 1, sub = step & 1;
        const int rbuf = step & 1, wbuf = rbuf ^ 1;

        float pv[8];
        if (kh == 0) {
            const float* Pt = g_P + ((size_t)t * R4 + (size_t)cell * 2048) * Bb;
#pragma unroll
            for (int q = 0; q < 8; ++q) {
                int u = q >> 2, gate = q & 3;
                pv[q] = Pt[(size_t)(gate * 512 + jA + u) * Bb + b];
            }
        }
        float xh = (sub && kh == 0) ? ldcg1(&g_H[rbuf][1][(Hh - 1) >> 2][b][3]) : 0.0f;

        if (step == 0) {
            float4 z = make_float4(0.f, 0.f, 0.f, 0.f);
            for (int i = tid; i < 128 * 32; i += NTHR) hs[i] = z;
        } else {
            const float4* src = (const float4*)&g_H[rbuf][cell][0][0][0];
            for (int i = tid; i < 128 * 32; i += NTHR) hs[i] = ldcg4(&src[i]);
        }
        __syncthreads();

        float acc[8];
#pragma unroll
        for (int q = 0; q < 8; ++q) acc[q] = 0.0f;
        const float4* hb = hs + b;
#pragma unroll 4
        for (int kq = kh * 64; kq < kh * 64 + 64; ++kq) {
            float4 hv = hb[kq * 32];
#pragma unroll
            for (int q = 0; q < 8; ++q) {
                float4 wv = wr4[q * 128 + kq];
                acc[q] += wv.x * hv.x;
                acc[q] += wv.y * hv.y;
                acc[q] += wv.z * hv.z;
                acc[q] += wv.w * hv.w;
            }
        }
#pragma unroll
        for (int q = 0; q < 8; ++q) redA[(w * 8 + q) * 32 + b] = acc[q];
        __syncthreads();

        if (kh == 0) {
            float h2v[2];
#pragma unroll
            for (int u = 0; u < 2; ++u) {
#pragma unroll
                for (int q = 0; q < 4; ++q) {
                    int qq = u * 4 + q;
                    acc[qq] += redA[((w + 4) * 8 + qq) * 32 + b];
                    acc[qq] += pv[qq] + xh * rs[qq];
                }
                float iv = acc[u*4+0], fv = acc[u*4+1], gv = acc[u*4+2], ov = acc[u*4+3];
                cst[u] = fsig(fv) * cst[u] + fsig(iv) * ftanh(gv);
                h2v[u] = fsig(ov) * ftanh(cst[u]);
            }
            stcg2((float2*)&g_H[wbuf][cell][jA >> 2][b][jA & 3],
                  make_float2(h2v[0], h2v[1]));
            if (is_xh) g_XH[sub][t][b] = h2v[1];
        }

        if (step == 2 * Tt - 1) break;
        __syncthreads();
        if (tid == 0) {
            asm volatile("membar.gl;" ::: "memory");
            atomicAdd(&g_bar, 1u);
            unsigned want = (unsigned)(step + 1) * NBLK;
            unsigned v;
            do {
                asm volatile("ld.acquire.gpu.global.u32 %0,[%1];" : "=r"(v) : "l"(&g_bar));
            } while (v < want);
        }
        __syncthreads();
    }
}

// =====================================================================
// Kernel 3: out = 1.5*u + 0.5*(xh1 + xh2)
// =====================================================================
__global__ __launch_bounds__(256) void epi_kernel(const float* __restrict__ U,
                                                  float* __restrict__ out)
{
    int idx = blockIdx.x * blockDim.x + threadIdx.x;
    if (idx >= Bb * Tt * Dd / 4) return;
    int t = (idx >> 7) & (Tt - 1);
    int b = idx >> 17;
    float s = 0.5f * (g_XH[0][t][b] + g_XH[1][t][b]);
    float4 u = ((const float4*)U)[idx];
    ((float4*)out)[idx] = make_float4(1.5f * u.x + s, 1.5f * u.y + s,
                                      1.5f * u.z + s, 1.5f * u.w + s);
}

extern "C" void kernel_launch(void* const* d_in, const int* in_sizes, int n_in,
                              void* d_out, int out_size) {
    const float* U     = (const float*)d_in[0];
    const float* wih_f = (const float*)d_in[1];
    const float* whh_f = (const float*)d_in[2];
    const float* bih_f = (const float*)d_in[3];
    const float* bhh_f = (const float*)d_in[4];
    const float* wih_b = (const float*)d_in[5];
    const float* whh_b = (const float*)d_in[6];
    const float* bih_b = (const float*)d_in[7];
    const float* bhh_b = (const float*)d_in[8];
    float* out = (float*)d_out;

    const int smem_sz = 65536 + 65536 + (8*8*32 + 32 + NTHR) * 4;
    cudaFuncSetAttribute(rec_kernel, cudaFuncAttributeMaxDynamicSharedMemorySize, smem_sz);

    void* bar_addr = nullptr;
    cudaGetSymbolAddress(&bar_addr, g_bar);
    cudaMemsetAsync(bar_addr, 0, sizeof(unsigned), 0);

    pre_kernel<<<dim3(32, Tt), 256>>>(U, wih_f, wih_b, bih_f, bhh_f, bih_b, bhh_b);
    rec_kernel<<<NBLK, NTHR, smem_sz>>>(whh_f, whh_b, wih_f, wih_b);
    epi_kernel<<<(Bb * Tt * Dd / 4 + 255) / 256, 256>>>(U, out);
}